// round 6
// baseline (speedup 1.0000x reference)
#include <cuda_runtime.h>
#include <cstdint>

// ---------------- problem constants ----------------
namespace {
constexpr int NB = 8;
constexpr int NQ = 500;
constexpr int NC = 256;     // channels
constexpr float SSCALE = 0.077f;

constexpr int QB   = 16;              // queries per block
constexpr int ROWS = 128;             // QB * 8 sampling pts (GEMM M)
constexpr int KCH  = 64;              // K-chunk
constexpr int NCH  = NC / KCH;        // 4
constexpr int THREADS = 512;          // 16 warps

constexpr int ASTR = 68;              // A row stride (floats): 68 % 32 == 4 -> conflict-free frags
constexpr int BSTR = 264;             // B row stride (floats): 264 % 32 == 8 -> conflict-free frags

constexpr int ABUF = ROWS * ASTR * 4;     // 34816 B per A buffer
constexpr int BBUF = KCH * BSTR * 4;      // 67584 B per B buffer

// dynamic smem byte offsets
constexpr int SM_A    = 0;                 // 2 * 34816  = 69632
constexpr int SM_B    = 69632;             // 2 * 67584  = 135168 (ends 204800)
constexpr int SM_PTS  = 204800;            // 128*2 floats
constexpr int SM_IDX  = 205824;            // 128 int4
constexpr int SM_WT   = 207872;            // 128 float4
constexpr int SM_B1S  = 209920;            // 256 floats
constexpr int SM_W2S  = 210944;            // 256*4 floats
constexpr int SM_PART = 215040;            // 128*4 floats
constexpr int SMEM_TOTAL = 217088;         // 212 KB -> 1 CTA/SM
}

__constant__ int c_hw[4] = {80, 40, 20, 10};
__constant__ int c_st[4] = {0, 6400, 8000, 8400};

__device__ __forceinline__ float tanh_fast(float x) {
    float r; asm("tanh.approx.f32 %0, %1;" : "=f"(r) : "f"(x)); return r;
}
__device__ __forceinline__ uint32_t smem_u32(const void* p) {
    uint32_t a;
    asm("{ .reg .u64 t; cvta.to.shared.u64 t, %1; cvt.u32.u64 %0, t; }" : "=r"(a) : "l"(p));
    return a;
}
// portable async copy (sm_80+)
__device__ __forceinline__ void cp_async16(uint32_t dst_smem, const void* src) {
    asm volatile("cp.async.cg.shared.global [%0], [%1], 16;" :: "r"(dst_smem), "l"(src));
}
#define CP_COMMIT() asm volatile("cp.async.commit_group;" ::: "memory")
#define CP_WAIT(n)  asm volatile("cp.async.wait_group %0;" :: "n"(n) : "memory")

// m16n8k8 tf32 MMA (portable PTX, sm_80+)
__device__ __forceinline__ void mma_tf32(float* c, const uint32_t* a, const uint32_t* b) {
    asm volatile(
        "mma.sync.aligned.m16n8k8.row.col.f32.tf32.tf32.f32 "
        "{%0,%1,%2,%3}, {%4,%5,%6,%7}, {%8,%9}, {%0,%1,%2,%3};"
        : "+f"(c[0]), "+f"(c[1]), "+f"(c[2]), "+f"(c[3])
        : "r"(a[0]), "r"(a[1]), "r"(a[2]), "r"(a[3]), "r"(b[0]), "r"(b[1]));
}

__global__ __launch_bounds__(THREADS, 1) void decoder_kernel(
    const float* __restrict__ ref_polys,   // (B,Q,8)
    const int*   __restrict__ ref_levels,  // (B,Q)
    const float* __restrict__ memory,      // (B,8500,256)
    const float* __restrict__ W1,          // (256,256)  [k][n]
    const float* __restrict__ b1,          // (256,)
    const float* __restrict__ W2,          // (256,4)
    const float* __restrict__ b2,          // (4,)
    float*       __restrict__ out)         // (B,Q,16,2)
{
    extern __shared__ char smem[];
    const uint32_t smb = smem_u32(smem);
    const int tid  = threadIdx.x;
    const int lane = tid & 31;
    const int wid  = tid >> 5;
    const int bq0  = blockIdx.x * QB;

    float* ptsS = (float*)(smem + SM_PTS);
    float* b1s  = (float*)(smem + SM_B1S);
    float* w2s  = (float*)(smem + SM_W2S);
    float* part = (float*)(smem + SM_PART);

    // ---- stage 1: bilinear setup per row (threads 0..127) ----
    if (tid < ROWS) {
        const int r = tid, g = r >> 3, s = r & 7;
        const int bq = bq0 + g;
        const int b  = bq / NQ;
        const float lam = s * (1.0f / 7.0f);
        const float* rp = ref_polys + bq * 8;
        float px = ((rp[0] * lam + rp[1]) * lam + rp[2]) * lam + rp[3];
        float py = ((rp[4] * lam + rp[5]) * lam + rp[6]) * lam + rp[7];
        px = 2.0f * (px - 0.5f);
        py = 2.0f * (py - 0.5f);
        ptsS[r * 2 + 0] = px;
        ptsS[r * 2 + 1] = py;

        const int lvl = ref_levels[bq];
        const int ww  = c_hw[lvl];
        const float gx = (px + 1.0f) * 0.5f * (float)ww - 0.5f;
        const float gy = (py + 1.0f) * 0.5f * (float)ww - 0.5f;
        const float x0f = floorf(gx), y0f = floorf(gy);
        const float wx1 = gx - x0f, wy1 = gy - y0f;
        const float wx0 = 1.0f - wx1, wy0 = 1.0f - wy1;
        const int x0 = (int)x0f, y0 = (int)y0f;
        const bool vx0 = (x0 >= 0) && (x0 < ww);
        const bool vx1 = (x0 >= -1) && (x0 < ww - 1);
        const bool vy0 = (y0 >= 0) && (y0 < ww);
        const bool vy1 = (y0 >= -1) && (y0 < ww - 1);
        const int x0c = min(max(x0, 0), ww - 1);
        const int x1c = min(max(x0 + 1, 0), ww - 1);
        const int y0c = min(max(y0, 0), ww - 1);
        const int y1c = min(max(y0 + 1, 0), ww - 1);
        const int base = b * 8500 + c_st[lvl];
        *(int4*)(smem + SM_IDX + r * 16) =
            make_int4((base + y0c * ww + x0c) * NC, (base + y0c * ww + x1c) * NC,
                      (base + y1c * ww + x0c) * NC, (base + y1c * ww + x1c) * NC);
        *(float4*)(smem + SM_WT + r * 16) =
            make_float4((vx0 && vy0) ? wy0 * wx0 : 0.0f, (vx1 && vy0) ? wy0 * wx1 : 0.0f,
                        (vx0 && vy1) ? wy1 * wx0 : 0.0f, (vx1 && vy1) ? wy1 * wx1 : 0.0f);
        ((float4*)part)[tid] = make_float4(0.f, 0.f, 0.f, 0.f);
    }
    if (tid < NC) b1s[tid] = b1[tid];
    if (tid < NC) ((float4*)w2s)[tid] = ((const float4*)W2)[tid];
    __syncthreads();

    // gather mapping: thread -> row r, quarter q (4 float4 per thread per chunk)
    const int gr = tid >> 2;           // 0..127
    const int gq = tid & 3;            // 0..3
    const int4   gii = *(const int4*)(smem + SM_IDX + gr * 16);
    const float4 gwv = *(const float4*)(smem + SM_WT + gr * 16);

    // ---- fill helpers (inline lambdas) ----
    auto gatherA = [&](int kc, float4* o) {
        const int c0 = kc * KCH + gq * 16;
#pragma unroll
        for (int i = 0; i < 4; ++i) {
            const int c = c0 + i * 4;
            const float4 v0 = __ldg((const float4*)(memory + gii.x + c));
            const float4 v1 = __ldg((const float4*)(memory + gii.y + c));
            const float4 v2 = __ldg((const float4*)(memory + gii.z + c));
            const float4 v3 = __ldg((const float4*)(memory + gii.w + c));
            o[i].x = gwv.x * v0.x + gwv.y * v1.x + gwv.z * v2.x + gwv.w * v3.x;
            o[i].y = gwv.x * v0.y + gwv.y * v1.y + gwv.z * v2.y + gwv.w * v3.y;
            o[i].z = gwv.x * v0.z + gwv.y * v1.z + gwv.z * v2.z + gwv.w * v3.z;
            o[i].w = gwv.x * v0.w + gwv.y * v1.w + gwv.z * v2.w + gwv.w * v3.w;
        }
    };
    auto storeA = [&](int p, const float4* o) {
        char* ab = smem + SM_A + p * ABUF;
#pragma unroll
        for (int i = 0; i < 4; ++i)
            *(float4*)(ab + (gr * ASTR + gq * 16 + i * 4) * 4) = o[i];
    };
    auto copyB = [&](int kc, int p) {
        const uint32_t bb = smb + SM_B + p * BBUF;
        const float* src = W1 + kc * KCH * NC;
#pragma unroll
        for (int i = 0; i < 8; ++i) {
            const int fi  = tid + i * THREADS;      // 0..4095
            const int row = fi >> 6;
            const int c4  = fi & 63;
            cp_async16(bb + (uint32_t)(row * BSTR + c4 * 4) * 4, src + row * NC + c4 * 4);
        }
    };

    // ---- warp tiling: mh = M half (64 rows), nq = 32-col slab ----
    const int mh = wid >> 3;           // 0..1
    const int nq = wid & 7;            // 0..7
    const int g  = lane >> 2;          // 0..7
    const int tg = lane & 3;           // 0..3

    float acc[4][4][4];
#pragma unroll
    for (int mt = 0; mt < 4; ++mt)
#pragma unroll
        for (int nt = 0; nt < 4; ++nt)
#pragma unroll
            for (int i = 0; i < 4; ++i) acc[mt][nt][i] = 0.f;

    // ---- prologue: fill chunks 0 and 1 ----
    {
        float4 a0[4];
        gatherA(0, a0); storeA(0, a0); copyB(0, 0); CP_COMMIT();
        float4 a1[4];
        gatherA(1, a1); storeA(1, a1); copyB(1, 1); CP_COMMIT();
    }
    CP_WAIT(1);
    __syncthreads();

    // ---- mainloop ----
#pragma unroll
    for (int kc = 0; kc < NCH; ++kc) {
        const int p = kc & 1;
        const bool pf = (kc + 2 < NCH);

        float4 ga[4];
        if (pf) gatherA(kc + 2, ga);    // LDGs in flight across the MMA below

        const uint32_t* As = (const uint32_t*)(smem + SM_A + p * ABUF);
        const uint32_t* Bs = (const uint32_t*)(smem + SM_B + p * BBUF);
#pragma unroll
        for (int ks = 0; ks < 8; ++ks) {
            const int k0 = ks * 8;
            uint32_t a[4][4];
#pragma unroll
            for (int mt = 0; mt < 4; ++mt) {
                const int rb = mh * 64 + mt * 16;
                a[mt][0] = As[(rb + g)     * ASTR + k0 + tg];
                a[mt][1] = As[(rb + g + 8) * ASTR + k0 + tg];
                a[mt][2] = As[(rb + g)     * ASTR + k0 + tg + 4];
                a[mt][3] = As[(rb + g + 8) * ASTR + k0 + tg + 4];
            }
            uint32_t b[4][2];
#pragma unroll
            for (int nt = 0; nt < 4; ++nt) {
                const int jb = nq * 32 + nt * 8 + g;
                b[nt][0] = Bs[(k0 + tg)     * BSTR + jb];
                b[nt][1] = Bs[(k0 + tg + 4) * BSTR + jb];
            }
#pragma unroll
            for (int mt = 0; mt < 4; ++mt)
#pragma unroll
                for (int nt = 0; nt < 4; ++nt)
                    mma_tf32(acc[mt][nt], a[mt], b[nt]);
        }
        __syncthreads();                    // all warps done reading buffer p

        if (pf) { storeA(p, ga); copyB(kc + 2, p); CP_COMMIT(); }
        if (kc + 1 < NCH) {
            if (pf) CP_WAIT(1); else CP_WAIT(0);
            __syncthreads();
        }
    }

    // ---- epilogue: h = tanh(v + b1); layer-2 partials; reduce ----
    float pp[4][2][4];
#pragma unroll
    for (int mt = 0; mt < 4; ++mt)
#pragma unroll
        for (int rh = 0; rh < 2; ++rh)
#pragma unroll
            for (int k = 0; k < 4; ++k) pp[mt][rh][k] = 0.f;

#pragma unroll
    for (int mt = 0; mt < 4; ++mt) {
#pragma unroll
        for (int nt = 0; nt < 4; ++nt) {
            const int cb = nq * 32 + nt * 8 + 2 * tg;
#pragma unroll
            for (int v = 0; v < 4; ++v) {
                const int rh  = v >> 1;
                const int col = cb + (v & 1);
                const float hv = tanh_fast(acc[mt][nt][v] + b1s[col]);
                const float4 w2v = *(const float4*)(w2s + col * 4);
                pp[mt][rh][0] = fmaf(hv, w2v.x, pp[mt][rh][0]);
                pp[mt][rh][1] = fmaf(hv, w2v.y, pp[mt][rh][1]);
                pp[mt][rh][2] = fmaf(hv, w2v.z, pp[mt][rh][2]);
                pp[mt][rh][3] = fmaf(hv, w2v.w, pp[mt][rh][3]);
            }
        }
    }
#pragma unroll
    for (int mt = 0; mt < 4; ++mt)
#pragma unroll
        for (int rh = 0; rh < 2; ++rh)
#pragma unroll
            for (int k = 0; k < 4; ++k) {
                float v = pp[mt][rh][k];
                v += __shfl_xor_sync(0xFFFFFFFFu, v, 1);
                v += __shfl_xor_sync(0xFFFFFFFFu, v, 2);
                if (tg == 0) {
                    const int row = mh * 64 + mt * 16 + rh * 8 + g;
                    atomicAdd(&part[row * 4 + k], v);    // 8 nq-warps sum here
                }
            }
    __syncthreads();

    // ---- final: off = S*tanh(part + b2) + pts ----
    if (tid < ROWS) {
        const int r = tid, qg = r >> 3, s = r & 7;
        const float px = ptsS[r * 2 + 0];
        const float py = ptsS[r * 2 + 1];
        float* o = out + (size_t)(bq0 + qg) * 32 + s * 4;
#pragma unroll
        for (int k = 0; k < 4; ++k) {
            const float logit = part[r * 4 + k] + __ldg(b2 + k);
            o[k] = SSCALE * tanh_fast(logit) + ((k & 1) ? py : px);
        }
    }
}

extern "C" void kernel_launch(void* const* d_in, const int* in_sizes, int n_in,
                              void* d_out, int out_size) {
    const float* ref_polys  = (const float*)d_in[0];
    const int*   ref_levels = (const int*)  d_in[1];
    const float* memory     = (const float*)d_in[2];
    const float* W1         = (const float*)d_in[3];
    const float* b1         = (const float*)d_in[4];
    const float* W2         = (const float*)d_in[5];
    const float* b2         = (const float*)d_in[6];
    float* out = (float*)d_out;

    static int configured = 0;
    if (!configured) {
        cudaFuncSetAttribute(decoder_kernel,
                             cudaFuncAttributeMaxDynamicSharedMemorySize, SMEM_TOTAL);
        configured = 1;
    }
    decoder_kernel<<<(NB * NQ) / QB, THREADS, SMEM_TOTAL>>>(
        ref_polys, ref_levels, memory, W1, b1, W2, b2, out);
}

// round 11
// speedup vs baseline: 1.2529x; 1.2529x over previous
#include <cuda_runtime.h>
#include <cstdint>

// ---------------- problem constants ----------------
namespace {
constexpr int NB = 8;
constexpr int NQ = 500;
constexpr int NC = 256;     // channels
constexpr float SSCALE = 0.077f;

constexpr int QB   = 8;               // queries per block
constexpr int ROWS = 64;              // QB * 8 sampling pts (GEMM M)
constexpr int KCH  = 32;              // K-chunk
constexpr int NCH  = NC / KCH;        // 8
constexpr int THREADS = 256;          // 8 warps

constexpr int ASTR = 36;              // A row stride (floats): 36 % 32 == 4 -> conflict-free frags
constexpr int BSTR = 264;             // B row stride (floats): 264 % 32 == 8 -> conflict-free frags

constexpr int ABUF = ROWS * ASTR * 4;     // 9216 B per A buffer
constexpr int BBUF = KCH * BSTR * 4;      // 33792 B per B buffer

// dynamic smem byte offsets
constexpr int SM_A    = 0;                 // 2 * 9216  = 18432
constexpr int SM_B    = 18432;             // 2 * 33792 = 67584 (ends 86016)
constexpr int SM_PTS  = 86016;             // 64*2 floats
constexpr int SM_IDX  = 86528;             // 64 int4
constexpr int SM_WT   = 87552;             // 64 float4
constexpr int SM_B1S  = 88576;             // 256 floats
constexpr int SM_W2S  = 89600;             // 256*4 floats
constexpr int SM_PART = 93696;             // 64*4 floats
constexpr int SMEM_TOTAL = 94720;          // 92.5 KB -> 2 CTAs/SM
}

__constant__ int c_hw[4] = {80, 40, 20, 10};
__constant__ int c_st[4] = {0, 6400, 8000, 8400};

__device__ __forceinline__ float tanh_fast(float x) {
    float r; asm("tanh.approx.f32 %0, %1;" : "=f"(r) : "f"(x)); return r;
}
__device__ __forceinline__ uint32_t smem_u32(const void* p) {
    uint32_t a;
    asm("{ .reg .u64 t; cvta.to.shared.u64 t, %1; cvt.u32.u64 %0, t; }" : "=r"(a) : "l"(p));
    return a;
}
// portable async copy (sm_80+)
__device__ __forceinline__ void cp_async16(uint32_t dst_smem, const void* src) {
    asm volatile("cp.async.cg.shared.global [%0], [%1], 16;" :: "r"(dst_smem), "l"(src));
}
#define CP_COMMIT() asm volatile("cp.async.commit_group;" ::: "memory")
#define CP_WAIT(n)  asm volatile("cp.async.wait_group %0;" :: "n"(n) : "memory")

// m16n8k8 tf32 MMA (portable PTX, sm_80+)
__device__ __forceinline__ void mma_tf32(float* c, const uint32_t* a, const uint32_t* b) {
    asm volatile(
        "mma.sync.aligned.m16n8k8.row.col.f32.tf32.tf32.f32 "
        "{%0,%1,%2,%3}, {%4,%5,%6,%7}, {%8,%9}, {%0,%1,%2,%3};"
        : "+f"(c[0]), "+f"(c[1]), "+f"(c[2]), "+f"(c[3])
        : "r"(a[0]), "r"(a[1]), "r"(a[2]), "r"(a[3]), "r"(b[0]), "r"(b[1]));
}

__global__ __launch_bounds__(THREADS, 2) void decoder_kernel(
    const float* __restrict__ ref_polys,   // (B,Q,8)
    const int*   __restrict__ ref_levels,  // (B,Q)
    const float* __restrict__ memory,      // (B,8500,256)
    const float* __restrict__ W1,          // (256,256)  [k][n]
    const float* __restrict__ b1,          // (256,)
    const float* __restrict__ W2,          // (256,4)
    const float* __restrict__ b2,          // (4,)
    float*       __restrict__ out)         // (B,Q,16,2)
{
    extern __shared__ char smem[];
    const uint32_t smb = smem_u32(smem);
    const int tid  = threadIdx.x;
    const int lane = tid & 31;
    const int wid  = tid >> 5;
    const int bq0  = blockIdx.x * QB;

    float* ptsS = (float*)(smem + SM_PTS);
    float* b1s  = (float*)(smem + SM_B1S);
    float* w2s  = (float*)(smem + SM_W2S);
    float* part = (float*)(smem + SM_PART);

    // ---- stage 1: bilinear setup per row (threads 0..63) ----
    if (tid < ROWS) {
        const int r = tid, g = r >> 3, s = r & 7;
        const int bq = bq0 + g;
        const int b  = bq / NQ;
        const float lam = s * (1.0f / 7.0f);
        const float* rp = ref_polys + bq * 8;
        float px = ((rp[0] * lam + rp[1]) * lam + rp[2]) * lam + rp[3];
        float py = ((rp[4] * lam + rp[5]) * lam + rp[6]) * lam + rp[7];
        px = 2.0f * (px - 0.5f);
        py = 2.0f * (py - 0.5f);
        ptsS[r * 2 + 0] = px;
        ptsS[r * 2 + 1] = py;

        const int lvl = ref_levels[bq];
        const int ww  = c_hw[lvl];
        const float gx = (px + 1.0f) * 0.5f * (float)ww - 0.5f;
        const float gy = (py + 1.0f) * 0.5f * (float)ww - 0.5f;
        const float x0f = floorf(gx), y0f = floorf(gy);
        const float wx1 = gx - x0f, wy1 = gy - y0f;
        const float wx0 = 1.0f - wx1, wy0 = 1.0f - wy1;
        const int x0 = (int)x0f, y0 = (int)y0f;
        const bool vx0 = (x0 >= 0) && (x0 < ww);
        const bool vx1 = (x0 >= -1) && (x0 < ww - 1);
        const bool vy0 = (y0 >= 0) && (y0 < ww);
        const bool vy1 = (y0 >= -1) && (y0 < ww - 1);
        const int x0c = min(max(x0, 0), ww - 1);
        const int x1c = min(max(x0 + 1, 0), ww - 1);
        const int y0c = min(max(y0, 0), ww - 1);
        const int y1c = min(max(y0 + 1, 0), ww - 1);
        const int base = b * 8500 + c_st[lvl];
        *(int4*)(smem + SM_IDX + r * 16) =
            make_int4((base + y0c * ww + x0c) * NC, (base + y0c * ww + x1c) * NC,
                      (base + y1c * ww + x0c) * NC, (base + y1c * ww + x1c) * NC);
        *(float4*)(smem + SM_WT + r * 16) =
            make_float4((vx0 && vy0) ? wy0 * wx0 : 0.0f, (vx1 && vy0) ? wy0 * wx1 : 0.0f,
                        (vx0 && vy1) ? wy1 * wx0 : 0.0f, (vx1 && vy1) ? wy1 * wx1 : 0.0f);
        ((float4*)part)[tid] = make_float4(0.f, 0.f, 0.f, 0.f);
    }
    b1s[tid] = b1[tid];
    ((float4*)w2s)[tid] = ((const float4*)W2)[tid];
    __syncthreads();

    // gather mapping: thread -> row gr (0..63), 8-channel slab gq (0..3)
    const int gr = tid >> 2;
    const int gq = tid & 3;
    const int4   gii = *(const int4*)(smem + SM_IDX + gr * 16);
    const float4 gwv = *(const float4*)(smem + SM_WT + gr * 16);

    auto gatherA = [&](int kc, float4* o) {
        const int c = kc * KCH + gq * 8;
        const float4 a0 = __ldg((const float4*)(memory + gii.x + c));
        const float4 a1 = __ldg((const float4*)(memory + gii.y + c));
        const float4 a2 = __ldg((const float4*)(memory + gii.z + c));
        const float4 a3 = __ldg((const float4*)(memory + gii.w + c));
        const float4 b0 = __ldg((const float4*)(memory + gii.x + c + 4));
        const float4 b1_ = __ldg((const float4*)(memory + gii.y + c + 4));
        const float4 b2_ = __ldg((const float4*)(memory + gii.z + c + 4));
        const float4 b3 = __ldg((const float4*)(memory + gii.w + c + 4));
        o[0].x = gwv.x * a0.x + gwv.y * a1.x + gwv.z * a2.x + gwv.w * a3.x;
        o[0].y = gwv.x * a0.y + gwv.y * a1.y + gwv.z * a2.y + gwv.w * a3.y;
        o[0].z = gwv.x * a0.z + gwv.y * a1.z + gwv.z * a2.z + gwv.w * a3.z;
        o[0].w = gwv.x * a0.w + gwv.y * a1.w + gwv.z * a2.w + gwv.w * a3.w;
        o[1].x = gwv.x * b0.x + gwv.y * b1_.x + gwv.z * b2_.x + gwv.w * b3.x;
        o[1].y = gwv.x * b0.y + gwv.y * b1_.y + gwv.z * b2_.y + gwv.w * b3.y;
        o[1].z = gwv.x * b0.z + gwv.y * b1_.z + gwv.z * b2_.z + gwv.w * b3.z;
        o[1].w = gwv.x * b0.w + gwv.y * b1_.w + gwv.z * b2_.w + gwv.w * b3.w;
    };
    auto storeA = [&](int p, const float4* o) {
        char* ab = smem + SM_A + p * ABUF;
        *(float4*)(ab + (gr * ASTR + gq * 8 + 0) * 4) = o[0];
        *(float4*)(ab + (gr * ASTR + gq * 8 + 4) * 4) = o[1];
    };
    auto copyB = [&](int kc, int p) {
        const uint32_t bb = smb + SM_B + p * BBUF;
        const float* src = W1 + kc * KCH * NC;
#pragma unroll
        for (int i = 0; i < 8; ++i) {
            const int fi  = tid + i * THREADS;      // 0..2047
            const int row = fi >> 6;                // 0..31
            const int c4  = fi & 63;
            cp_async16(bb + (uint32_t)(row * BSTR + c4 * 4) * 4, src + row * NC + c4 * 4);
        }
    };

    // ---- warp tiling: mh = M half (32 rows), nq = 64-col slab ----
    const int mh = wid & 1;            // 0..1
    const int nq = wid >> 1;           // 0..3
    const int g  = lane >> 2;          // 0..7
    const int tg = lane & 3;           // 0..3

    float acc[2][8][4];
#pragma unroll
    for (int mt = 0; mt < 2; ++mt)
#pragma unroll
        for (int nt = 0; nt < 8; ++nt)
#pragma unroll
            for (int i = 0; i < 4; ++i) acc[mt][nt][i] = 0.f;

    // ---- prologue: fill chunks 0 and 1 ----
    {
        float4 a0[2];
        gatherA(0, a0); storeA(0, a0); copyB(0, 0); CP_COMMIT();
        float4 a1[2];
        gatherA(1, a1); storeA(1, a1); copyB(1, 1); CP_COMMIT();
    }
    CP_WAIT(1);
    __syncthreads();

    // ---- mainloop: 8 chunks, depth-2 pipeline ----
#pragma unroll
    for (int kc = 0; kc < NCH; ++kc) {
        const int p = kc & 1;
        const bool pf = (kc + 2 < NCH);

        float4 ga[2];
        if (pf) gatherA(kc + 2, ga);     // LDG.128s issued ahead of MMA

        const uint32_t* As = (const uint32_t*)(smem + SM_A + p * ABUF);
        const uint32_t* Bs = (const uint32_t*)(smem + SM_B + p * BBUF);
#pragma unroll
        for (int ks = 0; ks < 4; ++ks) {
            const int k0 = ks * 8;
            uint32_t a[2][4];
#pragma unroll
            for (int mt = 0; mt < 2; ++mt) {
                const int rb = mh * 32 + mt * 16;
                a[mt][0] = As[(rb + g)     * ASTR + k0 + tg];
                a[mt][1] = As[(rb + g + 8) * ASTR + k0 + tg];
                a[mt][2] = As[(rb + g)     * ASTR + k0 + tg + 4];
                a[mt][3] = As[(rb + g + 8) * ASTR + k0 + tg + 4];
            }
            uint32_t b[8][2];
#pragma unroll
            for (int nt = 0; nt < 8; ++nt) {
                const int jb = nq * 64 + nt * 8 + g;
                b[nt][0] = Bs[(k0 + tg)     * BSTR + jb];
                b[nt][1] = Bs[(k0 + tg + 4) * BSTR + jb];
            }
#pragma unroll
            for (int mt = 0; mt < 2; ++mt)
#pragma unroll
                for (int nt = 0; nt < 8; ++nt)
                    mma_tf32(acc[mt][nt], a[mt], b[nt]);
        }
        __syncthreads();                    // buffer p fully consumed

        if (pf) { storeA(p, ga); copyB(kc + 2, p); CP_COMMIT(); }
        if (kc + 1 < NCH) {
            if (pf) CP_WAIT(1); else CP_WAIT(0);
            __syncthreads();
        }
    }

    // ---- epilogue: h = tanh(v + b1); layer-2 partials; reduce ----
    float pp[2][2][4];
#pragma unroll
    for (int mt = 0; mt < 2; ++mt)
#pragma unroll
        for (int rh = 0; rh < 2; ++rh)
#pragma unroll
            for (int k = 0; k < 4; ++k) pp[mt][rh][k] = 0.f;

#pragma unroll
    for (int mt = 0; mt < 2; ++mt) {
#pragma unroll
        for (int nt = 0; nt < 8; ++nt) {
            const int cb = nq * 64 + nt * 8 + 2 * tg;
#pragma unroll
            for (int v = 0; v < 4; ++v) {
                const int rh  = v >> 1;
                const int col = cb + (v & 1);
                const float hv = tanh_fast(acc[mt][nt][v] + b1s[col]);
                const float4 w2v = *(const float4*)(w2s + col * 4);
                pp[mt][rh][0] = fmaf(hv, w2v.x, pp[mt][rh][0]);
                pp[mt][rh][1] = fmaf(hv, w2v.y, pp[mt][rh][1]);
                pp[mt][rh][2] = fmaf(hv, w2v.z, pp[mt][rh][2]);
                pp[mt][rh][3] = fmaf(hv, w2v.w, pp[mt][rh][3]);
            }
        }
    }
#pragma unroll
    for (int mt = 0; mt < 2; ++mt)
#pragma unroll
        for (int rh = 0; rh < 2; ++rh)
#pragma unroll
            for (int k = 0; k < 4; ++k) {
                float v = pp[mt][rh][k];
                v += __shfl_xor_sync(0xFFFFFFFFu, v, 1);
                v += __shfl_xor_sync(0xFFFFFFFFu, v, 2);
                if (tg == 0) {
                    const int row = mh * 32 + mt * 16 + rh * 8 + g;
                    atomicAdd(&part[row * 4 + k], v);    // 4 nq-warps sum here
                }
            }
    __syncthreads();

    // ---- final: off = S*tanh(part + b2) + pts ----
    if (tid < ROWS) {
        const int r = tid, qg = r >> 3, s = r & 7;
        const float px = ptsS[r * 2 + 0];
        const float py = ptsS[r * 2 + 1];
        float* o = out + (size_t)(bq0 + qg) * 32 + s * 4;
#pragma unroll
        for (int k = 0; k < 4; ++k) {
            const float logit = part[r * 4 + k] + __ldg(b2 + k);
            o[k] = SSCALE * tanh_fast(logit) + ((k & 1) ? py : px);
        }
    }
}

extern "C" void kernel_launch(void* const* d_in, const int* in_sizes, int n_in,
                              void* d_out, int out_size) {
    const float* ref_polys  = (const float*)d_in[0];
    const int*   ref_levels = (const int*)  d_in[1];
    const float* memory     = (const float*)d_in[2];
    const float* W1         = (const float*)d_in[3];
    const float* b1         = (const float*)d_in[4];
    const float* W2         = (const float*)d_in[5];
    const float* b2         = (const float*)d_in[6];
    float* out = (float*)d_out;

    static int configured = 0;
    if (!configured) {
        cudaFuncSetAttribute(decoder_kernel,
                             cudaFuncAttributeMaxDynamicSharedMemorySize, SMEM_TOTAL);
        configured = 1;
    }
    decoder_kernel<<<(NB * NQ) / QB, THREADS, SMEM_TOTAL>>>(
        ref_polys, ref_levels, memory, W1, b1, W2, b2, out);
}

// round 15
// speedup vs baseline: 1.3517x; 1.0789x over previous
#include <cuda_runtime.h>
#include <cuda_bf16.h>
#include <cstdint>

// ---------------- problem constants ----------------
namespace {
constexpr int NB = 8;
constexpr int NQ = 500;
constexpr int NC = 256;
constexpr float SSCALE = 0.077f;

constexpr int QB   = 8;               // queries per block
constexpr int ROWS = 64;              // GEMM M tile
constexpr int KCH  = 64;              // K chunk (bf16)
constexpr int NCH  = NC / KCH;        // 4
constexpr int THREADS = 256;          // 8 warps

// row strides in halfwords; 72 hw = 144 B -> rows land on distinct 16B segs mod 128B
constexpr int ASTRH = 72;
constexpr int BSTRH = 72;
constexpr int ABUF  = ROWS * ASTRH * 2;   //  9216 B per A buffer
constexpr int BBUF  = NC * BSTRH * 2;     // 36864 B per B buffer

// dynamic smem layout (bytes)
constexpr int SM_A    = 0;                // 2 * 9216  = 18432
constexpr int SM_B    = 18432;            // 2 * 36864 = 73728 (ends 92160)
constexpr int SM_PTS  = 92160;            // 64*2 floats
constexpr int SM_IDX  = 92672;            // 64 int4
constexpr int SM_WT   = 93696;            // 64 float4
constexpr int SM_B1S  = 94720;            // 256 floats
constexpr int SM_W2S  = 95744;            // 256*4 floats
constexpr int SM_PART = 99840;            // 64*4 floats
constexpr int SMEM_TOTAL = 100864;        // ~98.5 KB -> 2 CTAs/SM
}

__constant__ int c_hw[4] = {80, 40, 20, 10};
__constant__ int c_st[4] = {0, 6400, 8000, 8400};

// W1 transposed to bf16 [n][k] (device-global scratch; allocation-free)
__device__ __nv_bfloat16 g_W1T[NC * NC];

__device__ __forceinline__ float tanh_fast(float x) {
    float r; asm("tanh.approx.f32 %0, %1;" : "=f"(r) : "f"(x)); return r;
}
__device__ __forceinline__ uint32_t smem_u32(const void* p) {
    uint32_t a;
    asm("{ .reg .u64 t; cvta.to.shared.u64 t, %1; cvt.u32.u64 %0, t; }" : "=r"(a) : "l"(p));
    return a;
}
__device__ __forceinline__ uint32_t pack_bf16(float lo, float hi) {
    uint32_t d;
    asm("cvt.rn.bf16x2.f32 %0, %1, %2;" : "=r"(d) : "f"(hi), "f"(lo));
    return d;
}
// portable async copy (sm_80+)
__device__ __forceinline__ void cp_async16(uint32_t dst_smem, const void* src) {
    asm volatile("cp.async.cg.shared.global [%0], [%1], 16;" :: "r"(dst_smem), "l"(src));
}
#define CP_COMMIT() asm volatile("cp.async.commit_group;" ::: "memory")
#define CP_WAIT(n)  asm volatile("cp.async.wait_group %0;" :: "n"(n) : "memory")

// ldmatrix x4 (portable sm_75+)
__device__ __forceinline__ void ldsm4(uint32_t* r, uint32_t addr) {
    asm volatile("ldmatrix.sync.aligned.m8n8.x4.shared.b16 {%0,%1,%2,%3}, [%4];"
                 : "=r"(r[0]), "=r"(r[1]), "=r"(r[2]), "=r"(r[3]) : "r"(addr));
}
// m16n8k16 bf16 MMA (portable sm_80+)
__device__ __forceinline__ void mma_bf16(float* c, const uint32_t* a, const uint32_t* b) {
    asm volatile(
        "mma.sync.aligned.m16n8k16.row.col.f32.bf16.bf16.f32 "
        "{%0,%1,%2,%3}, {%4,%5,%6,%7}, {%8,%9}, {%0,%1,%2,%3};"
        : "+f"(c[0]), "+f"(c[1]), "+f"(c[2]), "+f"(c[3])
        : "r"(a[0]), "r"(a[1]), "r"(a[2]), "r"(a[3]), "r"(b[0]), "r"(b[1]));
}

// ---------------- one-time W1 -> bf16 [n][k] transpose ----------------
__global__ void transpose_w1(const float* __restrict__ W1) {
    __shared__ float tile[32][33];
    const int tx = threadIdx.x, ty = threadIdx.y;   // (32, 8)
    const int bx = blockIdx.x, by = blockIdx.y;     // (8, 8): bx = n-block, by = k-block
#pragma unroll
    for (int i = 0; i < 4; ++i)
        tile[ty + 8 * i][tx] = W1[(by * 32 + ty + 8 * i) * NC + bx * 32 + tx];
    __syncthreads();
#pragma unroll
    for (int i = 0; i < 4; ++i)
        g_W1T[(bx * 32 + ty + 8 * i) * NC + by * 32 + tx] =
            __float2bfloat16(tile[tx][ty + 8 * i]);
}

// ---------------- main kernel ----------------
__global__ __launch_bounds__(THREADS, 2) void decoder_kernel(
    const float* __restrict__ ref_polys,   // (B,Q,8)
    const int*   __restrict__ ref_levels,  // (B,Q)
    const float* __restrict__ memory,      // (B,8500,256)
    const float* __restrict__ b1,          // (256,)
    const float* __restrict__ W2,          // (256,4)
    const float* __restrict__ b2,          // (4,)
    float*       __restrict__ out)         // (B,Q,16,2)
{
    extern __shared__ char smem[];
    const uint32_t smb = smem_u32(smem);
    const int tid  = threadIdx.x;
    const int lane = tid & 31;
    const int wid  = tid >> 5;
    const int bq0  = blockIdx.x * QB;

    float* ptsS = (float*)(smem + SM_PTS);
    float* b1s  = (float*)(smem + SM_B1S);
    float* w2s  = (float*)(smem + SM_W2S);
    float* part = (float*)(smem + SM_PART);

    // ---- stage 1: bilinear setup per row (threads 0..63) ----
    if (tid < ROWS) {
        const int r = tid, g = r >> 3, s = r & 7;
        const int bq = bq0 + g;
        const int b  = bq / NQ;
        const float lam = s * (1.0f / 7.0f);
        const float* rp = ref_polys + bq * 8;
        float px = ((rp[0] * lam + rp[1]) * lam + rp[2]) * lam + rp[3];
        float py = ((rp[4] * lam + rp[5]) * lam + rp[6]) * lam + rp[7];
        px = 2.0f * (px - 0.5f);
        py = 2.0f * (py - 0.5f);
        ptsS[r * 2 + 0] = px;
        ptsS[r * 2 + 1] = py;

        const int lvl = ref_levels[bq];
        const int ww  = c_hw[lvl];
        const float gx = (px + 1.0f) * 0.5f * (float)ww - 0.5f;
        const float gy = (py + 1.0f) * 0.5f * (float)ww - 0.5f;
        const float x0f = floorf(gx), y0f = floorf(gy);
        const float wx1 = gx - x0f, wy1 = gy - y0f;
        const float wx0 = 1.0f - wx1, wy0 = 1.0f - wy1;
        const int x0 = (int)x0f, y0 = (int)y0f;
        const bool vx0 = (x0 >= 0) && (x0 < ww);
        const bool vx1 = (x0 >= -1) && (x0 < ww - 1);
        const bool vy0 = (y0 >= 0) && (y0 < ww);
        const bool vy1 = (y0 >= -1) && (y0 < ww - 1);
        const int x0c = min(max(x0, 0), ww - 1);
        const int x1c = min(max(x0 + 1, 0), ww - 1);
        const int y0c = min(max(y0, 0), ww - 1);
        const int y1c = min(max(y0 + 1, 0), ww - 1);
        const int base = b * 8500 + c_st[lvl];
        *(int4*)(smem + SM_IDX + r * 16) =
            make_int4((base + y0c * ww + x0c) * NC, (base + y0c * ww + x1c) * NC,
                      (base + y1c * ww + x0c) * NC, (base + y1c * ww + x1c) * NC);
        *(float4*)(smem + SM_WT + r * 16) =
            make_float4((vx0 && vy0) ? wy0 * wx0 : 0.0f, (vx1 && vy0) ? wy0 * wx1 : 0.0f,
                        (vx0 && vy1) ? wy1 * wx0 : 0.0f, (vx1 && vy1) ? wy1 * wx1 : 0.0f);
        ((float4*)part)[tid] = make_float4(0.f, 0.f, 0.f, 0.f);
    }
    b1s[tid] = b1[tid];
    ((float4*)w2s)[tid] = ((const float4*)W2)[tid];
    __syncthreads();

    // gather mapping: thread -> row gr (0..63), 16-channel slab gq (0..3)
    const int gr = tid >> 2;
    const int gq = tid & 3;
    const int4   gii = *(const int4*)(smem + SM_IDX + gr * 16);
    const float4 gwv = *(const float4*)(smem + SM_WT + gr * 16);

    auto gatherA = [&](int kc, uint32_t* o /*8 bf16x2*/) {
        const int c0 = kc * KCH + gq * 16;
        float rr[16];
#pragma unroll
        for (int i = 0; i < 4; ++i) {
            const int cc = c0 + i * 4;
            const float4 v0 = __ldg((const float4*)(memory + gii.x + cc));
            const float4 v1 = __ldg((const float4*)(memory + gii.y + cc));
            const float4 v2 = __ldg((const float4*)(memory + gii.z + cc));
            const float4 v3 = __ldg((const float4*)(memory + gii.w + cc));
            rr[i*4+0] = gwv.x * v0.x + gwv.y * v1.x + gwv.z * v2.x + gwv.w * v3.x;
            rr[i*4+1] = gwv.x * v0.y + gwv.y * v1.y + gwv.z * v2.y + gwv.w * v3.y;
            rr[i*4+2] = gwv.x * v0.z + gwv.y * v1.z + gwv.z * v2.z + gwv.w * v3.z;
            rr[i*4+3] = gwv.x * v0.w + gwv.y * v1.w + gwv.z * v2.w + gwv.w * v3.w;
        }
#pragma unroll
        for (int j = 0; j < 8; ++j) o[j] = pack_bf16(rr[2*j], rr[2*j+1]);
    };
    auto storeA = [&](int p, const uint32_t* o) {
        char* ab = smem + SM_A + p * ABUF + gr * (ASTRH * 2) + gq * 32;
        *(uint4*)(ab)      = make_uint4(o[0], o[1], o[2], o[3]);
        *(uint4*)(ab + 16) = make_uint4(o[4], o[5], o[6], o[7]);
    };
    auto copyB = [&](int kc, int p) {
        const uint32_t bb = smb + SM_B + p * BBUF;
        const char* src = (const char*)g_W1T + kc * (KCH * 2);
#pragma unroll
        for (int i = 0; i < 8; ++i) {
            const int fi  = tid + i * THREADS;     // 0..2047
            const int row = fi >> 3;               // n: 0..255
            const int seg = fi & 7;                // 16B segment within 128B chunk-row
            cp_async16(bb + (uint32_t)(row * (BSTRH * 2) + seg * 16),
                       src + (size_t)row * (NC * 2) + seg * 16);
        }
    };

    // ---- warp tiling: mh = M half (32 rows), nq = 64-col slab ----
    const int mh = wid & 1;            // 0..1
    const int nq = wid >> 1;           // 0..3
    const int g  = lane >> 2;          // 0..7
    const int tg = lane & 3;           // 0..3
    const int lr  = lane & 15;         // A ldsm row
    const int lc  = lane >> 4;         // A ldsm k-half
    const int bm  = lane >> 3;         // B ldsm matrix id
    const int bnt = bm >> 1;           // n-tile within pair
    const int bkl = (bm & 1) * 8;      // k-half
    const int bro = lane & 7;          // B ldsm row

    float acc[2][8][4];
#pragma unroll
    for (int mt = 0; mt < 2; ++mt)
#pragma unroll
        for (int nt = 0; nt < 8; ++nt)
#pragma unroll
            for (int i = 0; i < 4; ++i) acc[mt][nt][i] = 0.f;

    // ---- prologue: fill chunks 0 and 1 ----
    {
        uint32_t a0[8];
        gatherA(0, a0); storeA(0, a0); copyB(0, 0); CP_COMMIT();
        uint32_t a1[8];
        gatherA(1, a1); storeA(1, a1); copyB(1, 1); CP_COMMIT();
    }
    CP_WAIT(1);
    __syncthreads();

    // ---- mainloop: 4 chunks, depth-2 pipeline ----
#pragma unroll
    for (int kc = 0; kc < NCH; ++kc) {
        const int p = kc & 1;
        const bool pf = (kc + 2 < NCH);

        uint32_t ga[8];
        if (pf) gatherA(kc + 2, ga);       // LDG.128s fly under MMA

        const uint32_t Ab = smb + SM_A + p * ABUF;
        const uint32_t Bb = smb + SM_B + p * BBUF;
#pragma unroll
        for (int ks = 0; ks < 4; ++ks) {
            uint32_t a[2][4];
#pragma unroll
            for (int mt = 0; mt < 2; ++mt)
                ldsm4(a[mt], Ab + (mh * 32 + mt * 16 + lr) * (ASTRH * 2)
                                + (ks * 16 + lc * 8) * 2);
            uint32_t b[8][2];
#pragma unroll
            for (int ntp = 0; ntp < 4; ++ntp) {
                uint32_t t[4];
                const int n = nq * 64 + (2 * ntp + bnt) * 8 + bro;
                ldsm4(t, Bb + n * (BSTRH * 2) + (ks * 16 + bkl) * 2);
                b[2*ntp  ][0] = t[0]; b[2*ntp  ][1] = t[1];
                b[2*ntp+1][0] = t[2]; b[2*ntp+1][1] = t[3];
            }
#pragma unroll
            for (int mt = 0; mt < 2; ++mt)
#pragma unroll
                for (int nt = 0; nt < 8; ++nt)
                    mma_bf16(acc[mt][nt], a[mt], b[nt]);
        }
        __syncthreads();                    // buffer p consumed

        if (pf) { storeA(p, ga); copyB(kc + 2, p); CP_COMMIT(); }
        if (kc + 1 < NCH) {
            if (pf) CP_WAIT(1); else CP_WAIT(0);
            __syncthreads();
        }
    }

    // ---- epilogue: h = tanh(v + b1); layer-2 partials; reduce ----
    float pp[2][2][4];
#pragma unroll
    for (int mt = 0; mt < 2; ++mt)
#pragma unroll
        for (int rh = 0; rh < 2; ++rh)
#pragma unroll
            for (int k = 0; k < 4; ++k) pp[mt][rh][k] = 0.f;

#pragma unroll
    for (int mt = 0; mt < 2; ++mt) {
#pragma unroll
        for (int nt = 0; nt < 8; ++nt) {
            const int cb = nq * 64 + nt * 8 + 2 * tg;
#pragma unroll
            for (int v = 0; v < 4; ++v) {
                const int rh  = v >> 1;
                const int col = cb + (v & 1);
                const float hv = tanh_fast(acc[mt][nt][v] + b1s[col]);
                const float4 w2v = *(const float4*)(w2s + col * 4);
                pp[mt][rh][0] = fmaf(hv, w2v.x, pp[mt][rh][0]);
                pp[mt][rh][1] = fmaf(hv, w2v.y, pp[mt][rh][1]);
                pp[mt][rh][2] = fmaf(hv, w2v.z, pp[mt][rh][2]);
                pp[mt][rh][3] = fmaf(hv, w2v.w, pp[mt][rh][3]);
            }
        }
    }
#pragma unroll
    for (int mt = 0; mt < 2; ++mt)
#pragma unroll
        for (int rh = 0; rh < 2; ++rh)
#pragma unroll
            for (int k = 0; k < 4; ++k) {
                float v = pp[mt][rh][k];
                v += __shfl_xor_sync(0xFFFFFFFFu, v, 1);
                v += __shfl_xor_sync(0xFFFFFFFFu, v, 2);
                if (tg == 0) {
                    const int row = mh * 32 + mt * 16 + rh * 8 + g;
                    atomicAdd(&part[row * 4 + k], v);    // 4 nq-warps sum here
                }
            }
    __syncthreads();

    // ---- final: off = S*tanh(part + b2) + pts ----
    if (tid < ROWS) {
        const int r = tid, qg = r >> 3, s = r & 7;
        const float px = ptsS[r * 2 + 0];
        const float py = ptsS[r * 2 + 1];
        float* o = out + (size_t)(bq0 + qg) * 32 + s * 4;
#pragma unroll
        for (int k = 0; k < 4; ++k) {
            const float logit = part[r * 4 + k] + __ldg(b2 + k);
            o[k] = SSCALE * tanh_fast(logit) + ((k & 1) ? py : px);
        }
    }
}

extern "C" void kernel_launch(void* const* d_in, const int* in_sizes, int n_in,
                              void* d_out, int out_size) {
    const float* ref_polys  = (const float*)d_in[0];
    const int*   ref_levels = (const int*)  d_in[1];
    const float* memory     = (const float*)d_in[2];
    const float* W1         = (const float*)d_in[3];
    const float* b1         = (const float*)d_in[4];
    const float* W2         = (const float*)d_in[5];
    const float* b2         = (const float*)d_in[6];
    float* out = (float*)d_out;

    static int configured = 0;
    if (!configured) {
        cudaFuncSetAttribute(decoder_kernel,
                             cudaFuncAttributeMaxDynamicSharedMemorySize, SMEM_TOTAL);
        configured = 1;
    }
    transpose_w1<<<dim3(8, 8), dim3(32, 8)>>>(W1);
    decoder_kernel<<<(NB * NQ) / QB, THREADS, SMEM_TOTAL>>>(
        ref_polys, ref_levels, memory, b1, W2, b2, out);
}